// round 6
// baseline (speedup 1.0000x reference)
#include <cuda_runtime.h>
#include <cuda_fp16.h>
#include <cstdint>

#define N_ 2
#define LQ_ 4000
#define C_ 256
#define M_ 8
#define L_ 4
#define P_ 4
#define D_ 32
#define LIN_ 5440   // 64*64 + 32*32 + 16*16 + 8*8

// Scratch (static device globals; no allocation allowed)
__device__ __half g_kv [N_ * LIN_ * M_ * 64];  // [N,Lin,M,{k[32]|v[32]}]
__device__ float  g_q  [N_ * LQ_ * C_];
__device__ float  g_off[N_ * LQ_ * C_];
__device__ __half g_att[N_ * LQ_ * C_];
__device__ __half g_qh [N_ * LQ_ * C_];
__device__ __half g_inh[N_ * LIN_ * C_];
__device__ __half g_wh [5 * C_ * C_];          // Wk, Wv, Wq, Woff, Wout

// ---------------------------------------------------------------------------
// fp32 -> fp16 converters
// ---------------------------------------------------------------------------
struct Cvt2 { const float* s0; const float* s1; __half* d0; __half* d1; int n0, n1; };
__global__ void f2h2_kernel(Cvt2 c) {
    const int which = blockIdx.y;
    const float* s = which ? c.s1 : c.s0;
    __half* d = which ? c.d1 : c.d0;
    const int n = which ? c.n1 : c.n0;
    int i = (blockIdx.x * blockDim.x + threadIdx.x) * 4;
    if (i < n) {
        float4 v = *reinterpret_cast<const float4*>(s + i);
        __half2* p = reinterpret_cast<__half2*>(d + i);
        p[0] = __floats2half2_rn(v.x, v.y);
        p[1] = __floats2half2_rn(v.z, v.w);
    }
}

struct W5 { const float* w[5]; };
__global__ void f2h5_kernel(W5 ws, __half* __restrict__ d) {
    int which = blockIdx.y;
    int i = (blockIdx.x * blockDim.x + threadIdx.x) * 4;   // exact: 65536 elems
    const float* s = ws.w[which];
    float4 v = *reinterpret_cast<const float4*>(s + i);
    __half2* p = reinterpret_cast<__half2*>(d + which * (C_ * C_) + i);
    p[0] = __floats2half2_rn(v.x, v.y);
    p[1] = __floats2half2_rn(v.z, v.w);
}

__device__ __forceinline__ uint32_t smem_u32(const void* p) {
    return static_cast<uint32_t>(__cvta_generic_to_shared(p));
}
__device__ __forceinline__ void cp16(uint32_t dst, const void* src) {
    asm volatile("cp.async.cg.shared.global [%0], [%1], 16;" :: "r"(dst), "l"(src));
}
__device__ __forceinline__ void cp_commit() {
    asm volatile("cp.async.commit_group;");
}
template<int NN>
__device__ __forceinline__ void cp_wait() {
    asm volatile("cp.async.wait_group %0;" :: "n"(NN));
}

// ---------------------------------------------------------------------------
// HMMA GEMM, fp16 inputs, 2-stage cp.async pipeline, fused dual-weight.
// Columns 0..255 use W[0], bias b0 -> output slot 0; 256..511 use W+65536,
// bias b1 -> slot 1 (wsel uniform per block since BN=64).
// MODE 0: dual fp32 outs.  MODE 1: kv interleave (half).  MODE 2: single fp32.
// ---------------------------------------------------------------------------
template<int MODE>
__global__ __launch_bounds__(256) void gemm_mma(
    const __half* __restrict__ A, const __half* __restrict__ W,
    const float* __restrict__ b0, const float* __restrict__ b1,
    void* __restrict__ out0, void* __restrict__ out1, int rows)
{
    __shared__ __half As[2][128 * 40];
    __shared__ __half Bs[2][32 * 64];

    const int tid = threadIdx.x;
    const int lane = tid & 31;
    const int wm = (tid >> 5) & 3;
    const int wn = tid >> 7;
    const int row0 = blockIdx.y * 128;
    const int col0 = blockIdx.x * 64;
    const int wsel = col0 >> 8;
    const int colw = col0 & 255;

    const int ar = tid >> 2;
    const int ac = tid & 3;
    const __half* Ag0 = A + (size_t)min(row0 + ar,      rows - 1) * 256 + ac * 8;
    const __half* Ag1 = A + (size_t)min(row0 + ar + 64, rows - 1) * 256 + ac * 8;
    const uint32_t sA0 = smem_u32(&As[0][ar * 40 + ac * 8]);
    const uint32_t sA1 = smem_u32(&As[0][(ar + 64) * 40 + ac * 8]);
    const int bk = tid >> 3;
    const int bc = tid & 7;
    const __half* Bg = W + wsel * 65536 + (size_t)bk * 256 + colw + bc * 8;
    const uint32_t sB = smem_u32(&Bs[0][bk * 64 + ((bc ^ (bk & 7)) * 8)]);

    const uint32_t stA = 128 * 40 * 2;
    const uint32_t stB = 32 * 64 * 2;

    cp16(sA0, Ag0);
    cp16(sA1, Ag1);
    cp16(sB,  Bg);
    cp_commit();

    float acc[2][4][4];
#pragma unroll
    for (int mt = 0; mt < 2; mt++)
#pragma unroll
        for (int nt = 0; nt < 4; nt++)
#pragma unroll
            for (int i = 0; i < 4; i++) acc[mt][nt][i] = 0.0f;

    const int ltile = lane >> 3;
    const int ltr   = lane & 7;
    const int a_row_base = wm * 32 + (ltile & 1) * 8 + ltr;
    const int a_ch_off   = ltile >> 1;
    const int b_k_base   = (ltile & 1) * 8 + ltr;
    const int b_ch_off   = ltile >> 1;

#pragma unroll
    for (int it = 0; it < 8; it++) {
        const int buf = it & 1;
        if (it < 7) {
            const int nbuf = buf ^ 1;
            const int koff = (it + 1) * 32;
            cp16(sA0 + nbuf * stA, Ag0 + koff);
            cp16(sA1 + nbuf * stA, Ag1 + koff);
            cp16(sB  + nbuf * stB, Bg + (size_t)koff * 256);
            cp_commit();
            cp_wait<1>();
        } else {
            cp_wait<0>();
        }
        __syncthreads();

        const __half* Ab = As[buf];
        const __half* Bb = Bs[buf];
#pragma unroll
        for (int ks = 0; ks < 2; ks++) {
            uint32_t a[2][4], b[2][4];
#pragma unroll
            for (int mt = 0; mt < 2; mt++) {
                const int row = a_row_base + mt * 16;
                const int ch  = ks * 2 + a_ch_off;
                uint32_t addr = smem_u32(&Ab[row * 40 + ch * 8]);
                asm volatile(
                    "ldmatrix.sync.aligned.m8n8.x4.shared.b16 {%0,%1,%2,%3}, [%4];"
                    : "=r"(a[mt][0]), "=r"(a[mt][1]), "=r"(a[mt][2]), "=r"(a[mt][3])
                    : "r"(addr));
            }
#pragma unroll
            for (int p = 0; p < 2; p++) {
                const int k = ks * 16 + b_k_base;
                const int c = wn * 4 + p * 2 + b_ch_off;
                uint32_t addr = smem_u32(&Bb[k * 64 + ((c ^ (k & 7)) * 8)]);
                asm volatile(
                    "ldmatrix.sync.aligned.m8n8.x4.trans.shared.b16 {%0,%1,%2,%3}, [%4];"
                    : "=r"(b[p][0]), "=r"(b[p][1]), "=r"(b[p][2]), "=r"(b[p][3])
                    : "r"(addr));
            }
#pragma unroll
            for (int mt = 0; mt < 2; mt++)
#pragma unroll
                for (int nt = 0; nt < 4; nt++) {
                    const uint32_t bb0 = b[nt >> 1][(nt & 1) * 2 + 0];
                    const uint32_t bb1 = b[nt >> 1][(nt & 1) * 2 + 1];
                    asm volatile(
                        "mma.sync.aligned.m16n8k16.row.col.f32.f16.f16.f32 "
                        "{%0,%1,%2,%3}, {%4,%5,%6,%7}, {%8,%9}, {%0,%1,%2,%3};"
                        : "+f"(acc[mt][nt][0]), "+f"(acc[mt][nt][1]),
                          "+f"(acc[mt][nt][2]), "+f"(acc[mt][nt][3])
                        : "r"(a[mt][0]), "r"(a[mt][1]), "r"(a[mt][2]), "r"(a[mt][3]),
                          "r"(bb0), "r"(bb1));
                }
        }
        __syncthreads();
    }

    // epilogue
    const int g  = lane >> 2;
    const int qd = lane & 3;
    const float* bp = wsel ? b1 : b0;
#pragma unroll
    for (int mt = 0; mt < 2; mt++) {
        const int rlo = row0 + wm * 32 + mt * 16 + g;
        const int rhi = rlo + 8;
#pragma unroll
        for (int nt = 0; nt < 4; nt++) {
            const int n = col0 + wn * 32 + nt * 8 + qd * 2;
            const int c = n & 255;
            const float2 bb = *reinterpret_cast<const float2*>(&bp[c]);
            float v0 = acc[mt][nt][0] + bb.x, v1 = acc[mt][nt][1] + bb.y;
            float v2 = acc[mt][nt][2] + bb.x, v3 = acc[mt][nt][3] + bb.y;
            if (MODE == 1) {
                const int oc = ((c >> 5) << 6) + (c & 31) + (wsel ? 32 : 0);
                __half* o = (__half*)out0;
                if (rlo < rows)
                    *reinterpret_cast<__half2*>(&o[(size_t)rlo * 512 + oc]) = __floats2half2_rn(v0, v1);
                if (rhi < rows)
                    *reinterpret_cast<__half2*>(&o[(size_t)rhi * 512 + oc]) = __floats2half2_rn(v2, v3);
            } else {
                float* o = (MODE == 2) ? (float*)out0 : (wsel ? (float*)out1 : (float*)out0);
                if (rlo < rows)
                    *reinterpret_cast<float2*>(&o[(size_t)rlo * 256 + c]) = make_float2(v0, v1);
                if (rhi < rows)
                    *reinterpret_cast<float2*>(&o[(size_t)rhi * 256 + c]) = make_float2(v2, v3);
            }
        }
    }
}

// ---------------------------------------------------------------------------
// Sampling + key-aware attention. One warp per (n, q, m).
// Phase 1: all 64 gathers (branchless, clamped) -> kp/sv registers.
// Phase 2: 16 pipelined butterfly reductions. Phase 3: softmax + output.
// ---------------------------------------------------------------------------
__global__ __launch_bounds__(256) void sample_attn_kernel(
    const float* __restrict__ ref)   // [N, Lq, L, 2]
{
    const int w = blockIdx.x * 8 + (threadIdx.x >> 5);
    const int lane = threadIdx.x & 31;
    if (w >= N_ * LQ_ * M_) return;

    const int m  = w & 7;
    const int nq = w >> 3;
    const int n  = nq / LQ_;

    const int is_v = lane >> 4;
    const int cl = (lane & 15) * 2;

    float2 qd = make_float2(0.0f, 0.0f);
    if (!is_v) qd = *reinterpret_cast<const float2*>(&g_q[(nq * M_ + m) * D_ + cl]);

    const float* offp = g_off + nq * 256 + m * 32;
    const float* refp = ref + nq * 8;

    const int HWs[4]    = {64, 32, 16, 8};
    const int starts[4] = {0, 4096, 5120, 5376};

    float kp[16], sv0[16], sv1[16];

    // ---- Phase 1: gathers (no warp-sync ops inside) ----
#pragma unroll
    for (int l = 0; l < L_; l++) {
        const float rx = refp[l * 2 + 0];
        const float ry = refp[l * 2 + 1];
        const int HW = HWs[l];
        const float fHW = (float)HW;
        const float fx = rx * fHW - 0.5f;
        const float fy = ry * fHW - 0.5f;
        const int base = (n * LIN_ + starts[l]) * M_ + m;

#pragma unroll
        for (int p = 0; p < P_; p++) {
            const int pi = l * 4 + p;
            const float x = fx + offp[pi * 2 + 0];
            const float y = fy + offp[pi * 2 + 1];
            const float x0f = floorf(x);
            const float y0f = floorf(y);
            const float txf = x - x0f;
            const float tyf = y - y0f;
            const int x0 = (int)x0f;
            const int y0 = (int)y0f;

            float s0 = 0.0f, s1 = 0.0f;
#pragma unroll
            for (int c = 0; c < 4; c++) {
                const int dx = c & 1;
                const int dy = c >> 1;
                const int xi = x0 + dx;
                const int yi = y0 + dy;
                const bool valid = (xi >= 0) & (xi < HW) & (yi >= 0) & (yi < HW);
                const int xc = min(max(xi, 0), HW - 1);
                const int yc = min(max(yi, 0), HW - 1);
                const float wx = dx ? txf : (1.0f - txf);
                const float wy = dy ? tyf : (1.0f - tyf);
                const float wgt = valid ? wx * wy : 0.0f;
                const int idx = (base + (yc * HW + xc) * M_) * 64 + lane * 2;
                const float2 f = __half22float2(
                    *reinterpret_cast<const __half2*>(&g_kv[idx]));
                s0 = fmaf(wgt, f.x, s0);
                s1 = fmaf(wgt, f.y, s1);
            }
            sv0[pi] = s0;
            sv1[pi] = s1;
            kp[pi] = fmaf(qd.x, s0, qd.y * s1);   // 0 in value lanes
        }
    }

    // ---- Phase 2: 16 butterfly reductions (pipelined) ----
#pragma unroll
    for (int i = 0; i < 16; i++) {
        float lg = kp[i];
#pragma unroll
        for (int s = 16; s > 0; s >>= 1)
            lg += __shfl_xor_sync(0xffffffffu, lg, s);
        kp[i] = lg * 0.17677669529663687f;   // 1/sqrt(32)
    }

    // ---- Phase 3: softmax + weighted sum ----
    float mx = kp[0];
#pragma unroll
    for (int i = 1; i < 16; i++) mx = fmaxf(mx, kp[i]);
    float ssum = 0.0f;
#pragma unroll
    for (int i = 0; i < 16; i++) {
        kp[i] = __expf(kp[i] - mx);
        ssum += kp[i];
    }
    const float inv = 1.0f / ssum;
    float o0 = 0.0f, o1 = 0.0f;
#pragma unroll
    for (int i = 0; i < 16; i++) {
        o0 = fmaf(kp[i], sv0[i], o0);
        o1 = fmaf(kp[i], sv1[i], o1);
    }

    if (is_v)
        *reinterpret_cast<__half2*>(&g_att[(nq * M_ + m) * D_ + cl]) =
            __floats2half2_rn(o0 * inv, o1 * inv);
}

// ---------------------------------------------------------------------------
extern "C" void kernel_launch(void* const* d_in, const int* in_sizes, int n_in,
                              void* d_out, int out_size)
{
    const float* query = (const float*)d_in[0];
    const float* ref   = (const float*)d_in[1];
    const float* inp   = (const float*)d_in[2];
    const float* Wv   = (const float*)d_in[5];
    const float* bv   = (const float*)d_in[6];
    const float* Wk   = (const float*)d_in[7];
    const float* bk   = (const float*)d_in[8];
    const float* Wq   = (const float*)d_in[9];
    const float* bq   = (const float*)d_in[10];
    const float* Woff = (const float*)d_in[11];
    const float* boff = (const float*)d_in[12];
    const float* Wout = (const float*)d_in[13];
    const float* bout = (const float*)d_in[14];
    float* out = (float*)d_out;

    void *pkv, *pq, *po, *pa, *pqh, *pinh, *pwh;
    cudaGetSymbolAddress(&pkv,  g_kv);
    cudaGetSymbolAddress(&pq,   g_q);
    cudaGetSymbolAddress(&po,   g_off);
    cudaGetSymbolAddress(&pa,   g_att);
    cudaGetSymbolAddress(&pqh,  g_qh);
    cudaGetSymbolAddress(&pinh, g_inh);
    cudaGetSymbolAddress(&pwh,  g_wh);

    const int rowsV = N_ * LIN_;   // 10880
    const int rowsQ = N_ * LQ_;    // 8000
    const int gyV = rowsV / 128;          // 85
    const int gyQ = (rowsQ + 127) / 128;  // 63

    const int nQ = rowsQ * 256;    // 2,048,000
    const int nV = rowsV * 256;    // 2,785,280

    Cvt2 cv;
    cv.s0 = inp;   cv.d0 = (__half*)pinh; cv.n0 = nV;
    cv.s1 = query; cv.d1 = (__half*)pqh;  cv.n1 = nQ;
    f2h2_kernel<<<dim3((nV / 4 + 255) / 256, 2), 256>>>(cv);
    W5 ws; ws.w[0] = Wk; ws.w[1] = Wv; ws.w[2] = Wq; ws.w[3] = Woff; ws.w[4] = Wout;
    f2h5_kernel<<<dim3(64, 5), 256>>>(ws, (__half*)pwh);

    const __half* wh = (const __half*)pwh;
    // fused K|V projection -> interleaved kv
    gemm_mma<1><<<dim3(8, gyV), 256>>>((const __half*)pinh, wh + 0 * 65536,
                                       bk, bv, pkv, nullptr, rowsV);
    // fused Q|offset projection
    gemm_mma<0><<<dim3(8, gyQ), 256>>>((const __half*)pqh, wh + 2 * 65536,
                                       bq, boff, pq, po, rowsQ);

    const int nwarps = N_ * LQ_ * M_;          // 64000
    sample_attn_kernel<<<(nwarps + 7) / 8, 256>>>(ref);

    // output projection
    gemm_mma<2><<<dim3(4, gyQ), 256>>>((const __half*)pa, wh + 4 * 65536,
                                       bout, bout, out, nullptr, rowsQ);
}

// round 7
// speedup vs baseline: 1.3273x; 1.3273x over previous
#include <cuda_runtime.h>
#include <cuda_fp16.h>
#include <cstdint>

#define N_ 2
#define LQ_ 4000
#define C_ 256
#define M_ 8
#define L_ 4
#define P_ 4
#define D_ 32
#define LIN_ 5440   // 64*64 + 32*32 + 16*16 + 8*8

// Scratch (static device globals; no allocation allowed)
__device__ __half g_kv [N_ * LIN_ * M_ * 64];  // [N,Lin,M,{k[32]|v[32]}]
__device__ float  g_q  [N_ * LQ_ * C_];
__device__ float  g_off[N_ * LQ_ * C_];
__device__ __half g_att[N_ * LQ_ * C_];
__device__ __half g_qh [N_ * LQ_ * C_];
__device__ __half g_inh[N_ * LIN_ * C_];
__device__ __half g_wh [5 * C_ * C_];          // Wk, Wv, Wq, Woff, Wout

// ---------------------------------------------------------------------------
// fp32 -> fp16 converters
// ---------------------------------------------------------------------------
struct Cvt2 { const float* s0; const float* s1; __half* d0; __half* d1; int n0, n1; };
__global__ void f2h2_kernel(Cvt2 c) {
    const int which = blockIdx.y;
    const float* s = which ? c.s1 : c.s0;
    __half* d = which ? c.d1 : c.d0;
    const int n = which ? c.n1 : c.n0;
    int i = (blockIdx.x * blockDim.x + threadIdx.x) * 4;
    if (i < n) {
        float4 v = *reinterpret_cast<const float4*>(s + i);
        __half2* p = reinterpret_cast<__half2*>(d + i);
        p[0] = __floats2half2_rn(v.x, v.y);
        p[1] = __floats2half2_rn(v.z, v.w);
    }
}

struct W5 { const float* w[5]; };
__global__ void f2h5_kernel(W5 ws, __half* __restrict__ d) {
    int which = blockIdx.y;
    int i = (blockIdx.x * blockDim.x + threadIdx.x) * 4;   // exact: 65536 elems
    const float* s = ws.w[which];
    float4 v = *reinterpret_cast<const float4*>(s + i);
    __half2* p = reinterpret_cast<__half2*>(d + which * (C_ * C_) + i);
    p[0] = __floats2half2_rn(v.x, v.y);
    p[1] = __floats2half2_rn(v.z, v.w);
}

__device__ __forceinline__ uint32_t smem_u32(const void* p) {
    return static_cast<uint32_t>(__cvta_generic_to_shared(p));
}
__device__ __forceinline__ void cp16(uint32_t dst, const void* src) {
    asm volatile("cp.async.cg.shared.global [%0], [%1], 16;" :: "r"(dst), "l"(src));
}
__device__ __forceinline__ void cp_commit() {
    asm volatile("cp.async.commit_group;");
}
template<int NN>
__device__ __forceinline__ void cp_wait() {
    asm volatile("cp.async.wait_group %0;" :: "n"(NN));
}

// ---------------------------------------------------------------------------
// HMMA GEMM, fp16 inputs, 2-stage cp.async pipeline, fused dual-weight.
// Columns 0..255 use W, bias b0 -> out slot 0; 256..511 use W+65536, b1 -> 1.
// MODE 0: dual fp32 outs.  MODE 1: kv interleave (half).  MODE 2: single fp32.
// ---------------------------------------------------------------------------
template<int MODE>
__global__ __launch_bounds__(256) void gemm_mma(
    const __half* __restrict__ A, const __half* __restrict__ W,
    const float* __restrict__ b0, const float* __restrict__ b1,
    void* __restrict__ out0, void* __restrict__ out1, int rows)
{
    __shared__ __half As[2][128 * 40];
    __shared__ __half Bs[2][32 * 64];

    const int tid = threadIdx.x;
    const int lane = tid & 31;
    const int wm = (tid >> 5) & 3;
    const int wn = tid >> 7;
    const int row0 = blockIdx.y * 128;
    const int col0 = blockIdx.x * 64;
    const int wsel = col0 >> 8;
    const int colw = col0 & 255;

    const int ar = tid >> 2;
    const int ac = tid & 3;
    const __half* Ag0 = A + (size_t)min(row0 + ar,      rows - 1) * 256 + ac * 8;
    const __half* Ag1 = A + (size_t)min(row0 + ar + 64, rows - 1) * 256 + ac * 8;
    const uint32_t sA0 = smem_u32(&As[0][ar * 40 + ac * 8]);
    const uint32_t sA1 = smem_u32(&As[0][(ar + 64) * 40 + ac * 8]);
    const int bk = tid >> 3;
    const int bc = tid & 7;
    const __half* Bg = W + wsel * 65536 + (size_t)bk * 256 + colw + bc * 8;
    const uint32_t sB = smem_u32(&Bs[0][bk * 64 + ((bc ^ (bk & 7)) * 8)]);

    const uint32_t stA = 128 * 40 * 2;
    const uint32_t stB = 32 * 64 * 2;

    cp16(sA0, Ag0);
    cp16(sA1, Ag1);
    cp16(sB,  Bg);
    cp_commit();

    float acc[2][4][4];
#pragma unroll
    for (int mt = 0; mt < 2; mt++)
#pragma unroll
        for (int nt = 0; nt < 4; nt++)
#pragma unroll
            for (int i = 0; i < 4; i++) acc[mt][nt][i] = 0.0f;

    const int ltile = lane >> 3;
    const int ltr   = lane & 7;
    const int a_row_base = wm * 32 + (ltile & 1) * 8 + ltr;
    const int a_ch_off   = ltile >> 1;
    const int b_k_base   = (ltile & 1) * 8 + ltr;
    const int b_ch_off   = ltile >> 1;

#pragma unroll
    for (int it = 0; it < 8; it++) {
        const int buf = it & 1;
        if (it < 7) {
            const int nbuf = buf ^ 1;
            const int koff = (it + 1) * 32;
            cp16(sA0 + nbuf * stA, Ag0 + koff);
            cp16(sA1 + nbuf * stA, Ag1 + koff);
            cp16(sB  + nbuf * stB, Bg + (size_t)koff * 256);
            cp_commit();
            cp_wait<1>();
        } else {
            cp_wait<0>();
        }
        __syncthreads();

        const __half* Ab = As[buf];
        const __half* Bb = Bs[buf];
#pragma unroll
        for (int ks = 0; ks < 2; ks++) {
            uint32_t a[2][4], b[2][4];
#pragma unroll
            for (int mt = 0; mt < 2; mt++) {
                const int row = a_row_base + mt * 16;
                const int ch  = ks * 2 + a_ch_off;
                uint32_t addr = smem_u32(&Ab[row * 40 + ch * 8]);
                asm volatile(
                    "ldmatrix.sync.aligned.m8n8.x4.shared.b16 {%0,%1,%2,%3}, [%4];"
                    : "=r"(a[mt][0]), "=r"(a[mt][1]), "=r"(a[mt][2]), "=r"(a[mt][3])
                    : "r"(addr));
            }
#pragma unroll
            for (int p = 0; p < 2; p++) {
                const int k = ks * 16 + b_k_base;
                const int c = wn * 4 + p * 2 + b_ch_off;
                uint32_t addr = smem_u32(&Bb[k * 64 + ((c ^ (k & 7)) * 8)]);
                asm volatile(
                    "ldmatrix.sync.aligned.m8n8.x4.trans.shared.b16 {%0,%1,%2,%3}, [%4];"
                    : "=r"(b[p][0]), "=r"(b[p][1]), "=r"(b[p][2]), "=r"(b[p][3])
                    : "r"(addr));
            }
#pragma unroll
            for (int mt = 0; mt < 2; mt++)
#pragma unroll
                for (int nt = 0; nt < 4; nt++) {
                    const uint32_t bb0 = b[nt >> 1][(nt & 1) * 2 + 0];
                    const uint32_t bb1 = b[nt >> 1][(nt & 1) * 2 + 1];
                    asm volatile(
                        "mma.sync.aligned.m16n8k16.row.col.f32.f16.f16.f32 "
                        "{%0,%1,%2,%3}, {%4,%5,%6,%7}, {%8,%9}, {%0,%1,%2,%3};"
                        : "+f"(acc[mt][nt][0]), "+f"(acc[mt][nt][1]),
                          "+f"(acc[mt][nt][2]), "+f"(acc[mt][nt][3])
                        : "r"(a[mt][0]), "r"(a[mt][1]), "r"(a[mt][2]), "r"(a[mt][3]),
                          "r"(bb0), "r"(bb1));
                }
        }
        __syncthreads();
    }

    const int g  = lane >> 2;
    const int qd = lane & 3;
    const float* bp = wsel ? b1 : b0;
#pragma unroll
    for (int mt = 0; mt < 2; mt++) {
        const int rlo = row0 + wm * 32 + mt * 16 + g;
        const int rhi = rlo + 8;
#pragma unroll
        for (int nt = 0; nt < 4; nt++) {
            const int n = col0 + wn * 32 + nt * 8 + qd * 2;
            const int c = n & 255;
            const float2 bb = *reinterpret_cast<const float2*>(&bp[c]);
            float v0 = acc[mt][nt][0] + bb.x, v1 = acc[mt][nt][1] + bb.y;
            float v2 = acc[mt][nt][2] + bb.x, v3 = acc[mt][nt][3] + bb.y;
            if (MODE == 1) {
                const int oc = ((c >> 5) << 6) + (c & 31) + (wsel ? 32 : 0);
                __half* o = (__half*)out0;
                if (rlo < rows)
                    *reinterpret_cast<__half2*>(&o[(size_t)rlo * 512 + oc]) = __floats2half2_rn(v0, v1);
                if (rhi < rows)
                    *reinterpret_cast<__half2*>(&o[(size_t)rhi * 512 + oc]) = __floats2half2_rn(v2, v3);
            } else {
                float* o = (MODE == 2) ? (float*)out0 : (wsel ? (float*)out1 : (float*)out0);
                if (rlo < rows)
                    *reinterpret_cast<float2*>(&o[(size_t)rlo * 256 + c]) = make_float2(v0, v1);
                if (rhi < rows)
                    *reinterpret_cast<float2*>(&o[(size_t)rhi * 256 + c]) = make_float2(v2, v3);
            }
        }
    }
}

// ---------------------------------------------------------------------------
// Sampling + key-aware attention. One warp per (n, q, m).
// R5 structure, but points processed in PAIRS: both points' gathers issued
// together (8 loads in flight), then two interleaved shfl reduction trees.
// ---------------------------------------------------------------------------
__global__ __launch_bounds__(256) void sample_attn_kernel(
    const float* __restrict__ ref)   // [N, Lq, L, 2]
{
    const int w = blockIdx.x * 8 + (threadIdx.x >> 5);
    const int lane = threadIdx.x & 31;
    if (w >= N_ * LQ_ * M_) return;

    const int m  = w & 7;
    const int nq = w >> 3;
    const int n  = nq / LQ_;

    const int is_v = lane >> 4;
    const int cl = (lane & 15) * 2;

    float2 qd = make_float2(0.0f, 0.0f);
    if (!is_v) qd = *reinterpret_cast<const float2*>(&g_q[(nq * M_ + m) * D_ + cl]);

    const float* offp = g_off + nq * 256 + m * 32;
    const float* refp = ref + nq * 8;

    const int HWs[4]    = {64, 32, 16, 8};
    const int starts[4] = {0, 4096, 5120, 5376};

    float logits[16], sv0[16], sv1[16];

#pragma unroll
    for (int l = 0; l < L_; l++) {
        const float rx = refp[l * 2 + 0];
        const float ry = refp[l * 2 + 1];
        const int HW = HWs[l];
        const float fHW = (float)HW;
        const float fx = rx * fHW - 0.5f;
        const float fy = ry * fHW - 0.5f;
        const int base = (n * LIN_ + starts[l]) * M_ + m;

#pragma unroll
        for (int pp = 0; pp < 2; pp++) {      // pairs of points
            const int pa = l * 4 + pp * 2;
            const int pb = pa + 1;

            // coords for both points
            const float xA = fx + offp[pa * 2 + 0];
            const float yA = fy + offp[pa * 2 + 1];
            const float xB = fx + offp[pb * 2 + 0];
            const float yB = fy + offp[pb * 2 + 1];
            const float xA0f = floorf(xA), yA0f = floorf(yA);
            const float xB0f = floorf(xB), yB0f = floorf(yB);
            const float txA = xA - xA0f, tyA = yA - yA0f;
            const float txB = xB - xB0f, tyB = yB - yB0f;
            const int xA0 = (int)xA0f, yA0 = (int)yA0f;
            const int xB0 = (int)xB0f, yB0 = (int)yB0f;

            float a0 = 0.0f, a1 = 0.0f, b0 = 0.0f, b1 = 0.0f;
#pragma unroll
            for (int c = 0; c < 4; c++) {
                const int dx = c & 1;
                const int dy = c >> 1;
                // point A corner
                {
                    const int xi = xA0 + dx, yi = yA0 + dy;
                    if (xi >= 0 && xi < HW && yi >= 0 && yi < HW) {
                        const float wgt = (dx ? txA : 1.0f - txA) * (dy ? tyA : 1.0f - tyA);
                        const int idx = (base + (yi * HW + xi) * M_) * 64 + lane * 2;
                        const float2 f = __half22float2(
                            *reinterpret_cast<const __half2*>(&g_kv[idx]));
                        a0 = fmaf(wgt, f.x, a0);
                        a1 = fmaf(wgt, f.y, a1);
                    }
                }
                // point B corner
                {
                    const int xi = xB0 + dx, yi = yB0 + dy;
                    if (xi >= 0 && xi < HW && yi >= 0 && yi < HW) {
                        const float wgt = (dx ? txB : 1.0f - txB) * (dy ? tyB : 1.0f - tyB);
                        const int idx = (base + (yi * HW + xi) * M_) * 64 + lane * 2;
                        const float2 f = __half22float2(
                            *reinterpret_cast<const __half2*>(&g_kv[idx]));
                        b0 = fmaf(wgt, f.x, b0);
                        b1 = fmaf(wgt, f.y, b1);
                    }
                }
            }
            sv0[pa] = a0; sv1[pa] = a1;
            sv0[pb] = b0; sv1[pb] = b1;

            float lgA = is_v ? 0.0f : fmaf(qd.x, a0, qd.y * a1);
            float lgB = is_v ? 0.0f : fmaf(qd.x, b0, qd.y * b1);
            // two independent butterfly trees, interleaved (dual-issue)
#pragma unroll
            for (int s = 16; s > 0; s >>= 1) {
                lgA += __shfl_xor_sync(0xffffffffu, lgA, s);
                lgB += __shfl_xor_sync(0xffffffffu, lgB, s);
            }
            logits[pa] = lgA * 0.17677669529663687f;
            logits[pb] = lgB * 0.17677669529663687f;
        }
    }

    float mx = logits[0];
#pragma unroll
    for (int i = 1; i < 16; i++) mx = fmaxf(mx, logits[i]);
    float ssum = 0.0f;
#pragma unroll
    for (int i = 0; i < 16; i++) {
        logits[i] = __expf(logits[i] - mx);
        ssum += logits[i];
    }
    const float inv = 1.0f / ssum;
    float o0 = 0.0f, o1 = 0.0f;
#pragma unroll
    for (int i = 0; i < 16; i++) {
        o0 = fmaf(logits[i], sv0[i], o0);
        o1 = fmaf(logits[i], sv1[i], o1);
    }

    if (is_v)
        *reinterpret_cast<__half2*>(&g_att[(nq * M_ + m) * D_ + cl]) =
            __floats2half2_rn(o0 * inv, o1 * inv);
}

// ---------------------------------------------------------------------------
extern "C" void kernel_launch(void* const* d_in, const int* in_sizes, int n_in,
                              void* d_out, int out_size)
{
    const float* query = (const float*)d_in[0];
    const float* ref   = (const float*)d_in[1];
    const float* inp   = (const float*)d_in[2];
    const float* Wv   = (const float*)d_in[5];
    const float* bv   = (const float*)d_in[6];
    const float* Wk   = (const float*)d_in[7];
    const float* bk   = (const float*)d_in[8];
    const float* Wq   = (const float*)d_in[9];
    const float* bq   = (const float*)d_in[10];
    const float* Woff = (const float*)d_in[11];
    const float* boff = (const float*)d_in[12];
    const float* Wout = (const float*)d_in[13];
    const float* bout = (const float*)d_in[14];
    float* out = (float*)d_out;

    void *pkv, *pq, *po, *pa, *pqh, *pinh, *pwh;
    cudaGetSymbolAddress(&pkv,  g_kv);
    cudaGetSymbolAddress(&pq,   g_q);
    cudaGetSymbolAddress(&po,   g_off);
    cudaGetSymbolAddress(&pa,   g_att);
    cudaGetSymbolAddress(&pqh,  g_qh);
    cudaGetSymbolAddress(&pinh, g_inh);
    cudaGetSymbolAddress(&pwh,  g_wh);

    const int rowsV = N_ * LIN_;   // 10880
    const int rowsQ = N_ * LQ_;    // 8000
    const int gyV = rowsV / 128;          // 85
    const int gyQ = (rowsQ + 127) / 128;  // 63

    const int nQ = rowsQ * 256;
    const int nV = rowsV * 256;

    Cvt2 cv;
    cv.s0 = inp;   cv.d0 = (__half*)pinh; cv.n0 = nV;
    cv.s1 = query; cv.d1 = (__half*)pqh;  cv.n1 = nQ;
    f2h2_kernel<<<dim3((nV / 4 + 255) / 256, 2), 256>>>(cv);
    W5 ws; ws.w[0] = Wk; ws.w[1] = Wv; ws.w[2] = Wq; ws.w[3] = Woff; ws.w[4] = Wout;
    f2h5_kernel<<<dim3(64, 5), 256>>>(ws, (__half*)pwh);

    const __half* wh = (const __half*)pwh;
    // fused K|V projection -> interleaved kv
    gemm_mma<1><<<dim3(8, gyV), 256>>>((const __half*)pinh, wh + 0 * 65536,
                                       bk, bv, pkv, nullptr, rowsV);
    // fused Q|offset projection
    gemm_mma<0><<<dim3(8, gyQ), 256>>>((const __half*)pqh, wh + 2 * 65536,
                                       bq, boff, pq, po, rowsQ);

    const int nwarps = N_ * LQ_ * M_;          // 64000
    sample_attn_kernel<<<(nwarps + 7) / 8, 256>>>(ref);

    // output projection
    gemm_mma<2><<<dim3(4, gyQ), 256>>>((const __half*)pa, wh + 4 * 65536,
                                       bout, bout, out, nullptr, rowsQ);
}